// round 1
// baseline (speedup 1.0000x reference)
#include <cuda_runtime.h>
#include <cstdint>

#define BB 32
#define TT 2048
#define LL 17
#define EE 128
#define VV 100000

// Scratch: emissions [B*T, 17]  (~4.45 MB)
__device__ float g_em[BB * TT * LL];
__device__ int g_is64;

// ---------------------------------------------------------------------------
// Detect whether `text` is stored as int64 or int32.
// If int64: first 4096 u64 words are all valid indices (< V).
// If int32: words combine two indices; high half ~never all-zero over 4096.
// Deterministic for fixed input.
// ---------------------------------------------------------------------------
__global__ void detect_kernel(const unsigned long long* __restrict__ t64) {
    int ok = 1;
    for (int i = threadIdx.x; i < 4096; i += blockDim.x) {
        if (t64[i] >= (unsigned long long)VV) ok = 0;
    }
    int allok = __syncthreads_and(ok);
    if (threadIdx.x == 0) g_is64 = allok;
}

// ---------------------------------------------------------------------------
// Emissions: em[token, l] = dot(emb[text[token]], W5[:, l]) + b5[l]
// One thread per token. W5 staged in shared, padded [E][20] for float4 access.
// ---------------------------------------------------------------------------
__device__ __forceinline__ void fma4(float4& a, float xe, const float4 w) {
    a.x += xe * w.x; a.y += xe * w.y; a.z += xe * w.z; a.w += xe * w.w;
}

__global__ void __launch_bounds__(128) emis_kernel(
    const void* __restrict__ textp,
    const float* __restrict__ emb,
    const float* __restrict__ W5,
    const float* __restrict__ b5)
{
    __shared__ float sW[EE * 20];
    __shared__ float sb[20];
    int tid = threadIdx.x;
    for (int i = tid; i < EE * 20; i += blockDim.x) sW[i] = 0.0f;
    if (tid < 20) sb[tid] = 0.0f;
    __syncthreads();
    for (int i = tid; i < EE * LL; i += blockDim.x) {
        int e = i / LL, l = i % LL;
        sW[e * 20 + l] = W5[i];
    }
    if (tid < LL) sb[tid] = b5[tid];
    __syncthreads();

    int token = blockIdx.x * blockDim.x + tid;
    int idx;
    if (g_is64) idx = (int)((const unsigned long long*)textp)[token];
    else        idx = ((const int*)textp)[token];
    idx = max(0, min(VV - 1, idx));

    const float4* row = (const float4*)(emb + (size_t)idx * EE);
    float4 a0 = *(const float4*)&sb[0];
    float4 a1 = *(const float4*)&sb[4];
    float4 a2 = *(const float4*)&sb[8];
    float4 a3 = *(const float4*)&sb[12];
    float4 a4 = *(const float4*)&sb[16];

#pragma unroll 4
    for (int e4 = 0; e4 < EE / 4; e4++) {
        float4 x = __ldg(&row[e4]);
        const float* wb = &sW[e4 * 4 * 20];
#pragma unroll
        for (int c = 0; c < 4; c++) {
            float xe = (c == 0) ? x.x : (c == 1) ? x.y : (c == 2) ? x.z : x.w;
            const float4* w4 = (const float4*)(wb + c * 20);
            fma4(a0, xe, w4[0]);
            fma4(a1, xe, w4[1]);
            fma4(a2, xe, w4[2]);
            fma4(a3, xe, w4[3]);
            fma4(a4, xe, w4[4]);
        }
    }

    float* o = g_em + (size_t)token * LL;
    o[0] = a0.x; o[1] = a0.y; o[2] = a0.z; o[3] = a0.w;
    o[4] = a1.x; o[5] = a1.y; o[6] = a1.z; o[7] = a1.w;
    o[8] = a2.x; o[9] = a2.y; o[10] = a2.z; o[11] = a2.w;
    o[12] = a3.x; o[13] = a3.y; o[14] = a3.z; o[15] = a3.w;
    o[16] = a4.x;
}

// ---------------------------------------------------------------------------
// argmax over 17 values with FIRST-index tie-break (matches jnp.argmax).
// Balanced tree; every comparison keeps the left (lower-index) side on ties.
// ---------------------------------------------------------------------------
__device__ __forceinline__ void argmax17(const float* s, float& bv, int& bi) {
    float v[9]; int ix[9];
#pragma unroll
    for (int k = 0; k < 8; k++) {
        bool g = s[2 * k + 1] > s[2 * k];
        v[k]  = g ? s[2 * k + 1] : s[2 * k];
        ix[k] = g ? 2 * k + 1 : 2 * k;
    }
    v[8] = s[16]; ix[8] = 16;
#pragma unroll
    for (int k = 0; k < 4; k++) {
        bool g = v[2 * k + 1] > v[2 * k];
        v[k]  = g ? v[2 * k + 1] : v[2 * k];
        ix[k] = g ? ix[2 * k + 1] : ix[2 * k];
    }
    { bool g = v[1] > v[0]; v[0] = g ? v[1] : v[0]; ix[0] = g ? ix[1] : ix[0]; }
    { bool g = v[3] > v[2]; v[2] = g ? v[3] : v[2]; ix[2] = g ? ix[3] : ix[2]; }
    { bool g = v[2] > v[0]; v[0] = g ? v[2] : v[0]; ix[0] = g ? ix[2] : ix[0]; }
    { bool g = v[8] > v[0]; v[0] = g ? v[8] : v[0]; ix[0] = g ? ix[8] : ix[0]; }
    bv = v[0]; bi = ix[0];
}

// ---------------------------------------------------------------------------
// Viterbi: one warp per batch. Lane l owns label l (l<17).
// Forward: alpha broadcast via shfl; backpointers to shared; survivor
// composition `c` checkpointed every 128 steps so backtracking splits into
// 16 parallel chunk walks.
// ---------------------------------------------------------------------------
__global__ void __launch_bounds__(32, 1) viterbi_kernel(
    const float* __restrict__ trans, float* __restrict__ out)
{
    __shared__ unsigned char bp[(TT - 1) * LL];   // 34799 B
    __shared__ unsigned char comp[15 * LL];       // checkpoint maps
    __shared__ unsigned char sbt[16];             // chunk-boundary tags

    const int b = blockIdx.x;
    const int l = threadIdx.x;
    const int le = (l < LL) ? l : 0;

    float trc[LL];
#pragma unroll
    for (int j = 0; j < LL; j++) trc[j] = trans[j * LL + le];

    const float* em = g_em + (size_t)b * TT * LL;
    float alpha = (l < LL) ? em[le] : -3.0e38f;
    int c = le;
    float em_next = em[1 * LL + le];

    for (int t = 1; t < TT; t++) {
        float em_cur = em_next;
        if (t + 1 < TT) em_next = em[(t + 1) * LL + le];

        float s[LL];
#pragma unroll
        for (int j = 0; j < LL; j++)
            s[j] = __shfl_sync(0xFFFFFFFFu, alpha, j) + trc[j];

        float best; int bi;
        argmax17(s, best, bi);
        alpha = best + em_cur;

        if (l < LL) bp[(t - 1) * LL + l] = (unsigned char)bi;
        c = __shfl_sync(0xFFFFFFFFu, c, bi);
        if ((t & 127) == 0) {                 // checkpoint at t = 128..1920
            if (l < LL) comp[((t >> 7) - 1) * LL + l] = (unsigned char)c;
            c = le;
        }
    }

    // Final (score, last_tag), first-index tie-break
    float fs[LL];
#pragma unroll
    for (int j = 0; j < LL; j++)
        fs[j] = __shfl_sync(0xFFFFFFFFu, alpha, j);
    float score; int last_tag;
    argmax17(fs, score, last_tag);

    // Tag at t=1920 from the final (partial-chunk) survivor composition
    int t1920 = __shfl_sync(0xFFFFFFFFu, c, last_tag);

    __syncwarp();
    if (l == 0) {
        sbt[15] = (unsigned char)t1920;
        int cur = t1920;
        for (int i = 14; i >= 0; i--) {       // boundary tags via checkpoint maps
            cur = comp[i * LL + cur];
            sbt[i] = (unsigned char)cur;
        }
        out[BB * TT + b] = score;             // score
        out[BB * TT + BB + b] = (float)TT;    // text_lens
    }
    __syncwarp();

    // 16 parallel chunk walks (lane i owns times [i*128, (i+1)*128))
    float* otags = out + (size_t)b * TT;
    if (l < 16) {
        int i = l;
        int cur, tend;
        if (i == 15) {
            cur = last_tag;
            otags[TT - 1] = (float)cur;
            tend = TT - 1;
        } else {
            cur = sbt[i + 1];
            tend = (i + 1) * 128;
        }
        for (int t = tend; t > i * 128; t--) {
            cur = bp[(t - 1) * LL + cur];
            otags[t - 1] = (float)cur;
        }
    }
}

// ---------------------------------------------------------------------------
extern "C" void kernel_launch(void* const* d_in, const int* in_sizes, int n_in,
                              void* d_out, int out_size)
{
    (void)in_sizes; (void)n_in; (void)out_size;
    const void*  text = d_in[0];
    const float* emb  = (const float*)d_in[1];
    const float* W5   = (const float*)d_in[2];
    const float* b5   = (const float*)d_in[3];
    const float* trans= (const float*)d_in[4];
    float* out = (float*)d_out;

    detect_kernel<<<1, 256>>>((const unsigned long long*)text);
    emis_kernel<<<(BB * TT) / 128, 128>>>(text, emb, W5, b5);
    viterbi_kernel<<<BB, 32>>>(trans, out);
}

// round 3
// speedup vs baseline: 2.2873x; 2.2873x over previous
#include <cuda_runtime.h>
#include <cstdint>

#define BB 32
#define TT 2048
#define LL 17
#define EE 128
#define VV 100000
#define SS 128        // chunk length for backtracking
#define CC 16         // number of chunks (TT / SS)

// Scratch
__device__ float g_em[BB * TT * LL + 32];       // emissions [b][t][17] (+pad for prefetch overrun)
__device__ float g_alpha[BB * TT * LL];         // forward alphas [b][t][17]
__device__ unsigned char g_comp[BB * CC * LL];  // chunk survivor maps
__device__ unsigned char g_btag[BB * 17];       // boundary tags [b][c]=tag[128c], [b][16]=last_tag
__device__ int g_is64;

// ---------------------------------------------------------------------------
// int64-vs-int32 detection for `text` (deterministic).
// ---------------------------------------------------------------------------
__global__ void detect_kernel(const unsigned long long* __restrict__ t64) {
    int ok = 1;
    for (int i = threadIdx.x; i < 512; i += blockDim.x)
        if (t64[i] >= (unsigned long long)VV) ok = 0;
    int allok = __syncthreads_and(ok);
    if (threadIdx.x == 0) g_is64 = allok;
}

// ---------------------------------------------------------------------------
// Emissions: em[token][l] = dot(emb[text[token]], W5[:,l]) + b5[l]
// ---------------------------------------------------------------------------
__device__ __forceinline__ void fma4(float4& a, float xe, const float4 w) {
    a.x += xe * w.x; a.y += xe * w.y; a.z += xe * w.z; a.w += xe * w.w;
}

__global__ void __launch_bounds__(128) emis_kernel(
    const void* __restrict__ textp,
    const float* __restrict__ emb,
    const float* __restrict__ W5,
    const float* __restrict__ b5)
{
    __shared__ float sW[EE * 20];
    __shared__ float sb[20];
    int tid = threadIdx.x;
    for (int i = tid; i < EE * 20; i += blockDim.x) sW[i] = 0.0f;
    if (tid < 20) sb[tid] = 0.0f;
    __syncthreads();
    for (int i = tid; i < EE * LL; i += blockDim.x) {
        int e = i / LL, l = i % LL;
        sW[e * 20 + l] = W5[i];
    }
    if (tid < LL) sb[tid] = b5[tid];
    __syncthreads();

    int token = blockIdx.x * blockDim.x + tid;
    int idx;
    if (g_is64) idx = (int)((const unsigned long long*)textp)[token];
    else        idx = ((const int*)textp)[token];
    idx = max(0, min(VV - 1, idx));

    const float4* row = (const float4*)(emb + (size_t)idx * EE);
    float4 a0 = *(const float4*)&sb[0];
    float4 a1 = *(const float4*)&sb[4];
    float4 a2 = *(const float4*)&sb[8];
    float4 a3 = *(const float4*)&sb[12];
    float4 a4 = *(const float4*)&sb[16];

#pragma unroll 4
    for (int e4 = 0; e4 < EE / 4; e4++) {
        float4 x = __ldg(&row[e4]);
        const float* wb = &sW[e4 * 4 * 20];
#pragma unroll
        for (int c = 0; c < 4; c++) {
            float xe = (c == 0) ? x.x : (c == 1) ? x.y : (c == 2) ? x.z : x.w;
            const float4* w4 = (const float4*)(wb + c * 20);
            fma4(a0, xe, w4[0]);
            fma4(a1, xe, w4[1]);
            fma4(a2, xe, w4[2]);
            fma4(a3, xe, w4[3]);
            fma4(a4, xe, w4[4]);
        }
    }

    float* o = g_em + (size_t)token * LL;
    o[0] = a0.x; o[1] = a0.y; o[2] = a0.z; o[3] = a0.w;
    o[4] = a1.x; o[5] = a1.y; o[6] = a1.z; o[7] = a1.w;
    o[8] = a2.x; o[9] = a2.y; o[10] = a2.z; o[11] = a2.w;
    o[12] = a3.x; o[13] = a3.y; o[14] = a3.z; o[15] = a3.w;
    o[16] = a4.x;
}

// ---------------------------------------------------------------------------
// argmax over 17 values, FIRST-index tie-break (matches jnp.argmax).
// ---------------------------------------------------------------------------
__device__ __forceinline__ void argmax17(const float* s, float& bv, int& bi) {
    float v[9]; int ix[9];
#pragma unroll
    for (int k = 0; k < 8; k++) {
        bool g = s[2 * k + 1] > s[2 * k];
        v[k]  = g ? s[2 * k + 1] : s[2 * k];
        ix[k] = g ? 2 * k + 1 : 2 * k;
    }
    v[8] = s[16]; ix[8] = 16;
#pragma unroll
    for (int k = 0; k < 4; k++) {
        bool g = v[2 * k + 1] > v[2 * k];
        v[k]  = g ? v[2 * k + 1] : v[2 * k];
        ix[k] = g ? ix[2 * k + 1] : ix[2 * k];
    }
    { bool g = v[1] > v[0]; v[0] = g ? v[1] : v[0]; ix[0] = g ? ix[1] : ix[0]; }
    { bool g = v[3] > v[2]; v[2] = g ? v[3] : v[2]; ix[2] = g ? ix[3] : ix[2]; }
    { bool g = v[2] > v[0]; v[0] = g ? v[2] : v[0]; ix[0] = g ? ix[2] : ix[0]; }
    { bool g = v[8] > v[0]; v[0] = g ? v[8] : v[0]; ix[0] = g ? ix[8] : ix[0]; }
    bv = v[0]; bi = ix[0];
}

// Max-only step: returns max_j(shfl(alpha,j) + trc[j]). max is exactly
// associative so any reduction order gives the bitwise reference value.
__device__ __forceinline__ float step_max(float alpha, const float* trc) {
    float s[LL];
#pragma unroll
    for (int j = 0; j < LL; j++)
        s[j] = __shfl_sync(0xFFFFFFFFu, alpha, j) + trc[j];
    float v[9];
#pragma unroll
    for (int k = 0; k < 8; k++) v[k] = fmaxf(s[2 * k], s[2 * k + 1]);
    v[8] = s[16];
#pragma unroll
    for (int k = 0; k < 4; k++) v[k] = fmaxf(v[2 * k], v[2 * k + 1]);
    v[0] = fmaxf(v[0], v[1]); v[2] = fmaxf(v[2], v[3]);
    v[0] = fmaxf(v[0], v[2]);
    return fmaxf(v[0], v[8]);
}

// ---------------------------------------------------------------------------
// Forward chain: one warp per batch, lane = label. Max-only (no argmax),
// depth-16 em prefetch ring, stores alpha vector per step.
// ---------------------------------------------------------------------------
__global__ void __launch_bounds__(32, 1) forward_kernel(
    const float* __restrict__ trans)
{
    const int b = blockIdx.x;
    const int l = threadIdx.x;
    const int le = (l < LL) ? l : 0;

    float trc[LL];
#pragma unroll
    for (int j = 0; j < LL; j++) trc[j] = trans[j * LL + le];

    const float* em = g_em + (size_t)b * TT * LL;
    float alpha = (l < LL) ? em[le] : -3.0e38f;
    float* pa = g_alpha + (size_t)b * TT * LL + l;
    if (l < LL) *pa = alpha;       // alpha[0]
    pa += LL;

    // prefetch ring: ring[i] = em[t][le] for t = 1..16
    float ring[16];
    const float* pe = em + LL + le;
#pragma unroll
    for (int i = 0; i < 16; i++) ring[i] = __ldg(pe + i * LL);
    const float* pf = pe + 16 * LL;

    // main: 127 blocks of 16 steps (t = 1..2032)
    for (int blk = 0; blk < 127; blk++) {
#pragma unroll
        for (int u = 0; u < 16; u++) {
            float emc = ring[u];
            ring[u] = __ldg(pf); pf += LL;   // fetch t+16 (pad covers overrun)
            alpha = step_max(alpha, trc) + emc;
            if (l < LL) *pa = alpha;
            pa += LL;
        }
    }
    // tail: t = 2033..2047
#pragma unroll
    for (int u = 0; u < 15; u++) {
        alpha = step_max(alpha, trc) + ring[u];
        if (l < LL) *pa = alpha;
        pa += LL;
    }
}

// ---------------------------------------------------------------------------
// Shared helper: stage a chunk's alphas + T, recompute its backpointers
// (bitwise identical to reference: same adds, same tie-break tree).
// bpS[i][l] = bp at time t = t0+1+i. Returns nbp.
// ---------------------------------------------------------------------------
__device__ __forceinline__ int stage_and_bp(
    int b, int c, float* aS, float* tS, unsigned char* bpS,
    const float* __restrict__ trans)
{
    const int tid = threadIdx.x;
    const int t0 = c * SS;
    const int nrows = (c == CC - 1) ? SS : (SS + 1);   // alpha rows t0..t0+nrows-1
    const int nbp   = (c == CC - 1) ? (SS - 1) : SS;

    const float* src = g_alpha + ((size_t)b * TT + t0) * LL;
    for (int i = tid; i < nrows * LL; i += blockDim.x) aS[i] = src[i];
    for (int i = tid; i < LL * LL; i += blockDim.x) tS[i] = trans[i];
    __syncthreads();

    if (tid < nbp) {
        float a[LL];
#pragma unroll
        for (int k = 0; k < LL; k++) a[k] = aS[tid * LL + k];
#pragma unroll 1
        for (int lcur = 0; lcur < LL; lcur++) {
            float s[LL];
#pragma unroll
            for (int k = 0; k < LL; k++) s[k] = a[k] + tS[k * LL + lcur];
            float bv; int bi;
            argmax17(s, bv, bi);
            bpS[tid * LL + lcur] = (unsigned char)bi;
        }
    }
    __syncthreads();
    return nbp;
}

// ---------------------------------------------------------------------------
// Chunk survivor composition: map tag[chunk end] -> tag[chunk start].
// ---------------------------------------------------------------------------
__global__ void __launch_bounds__(128) comp_kernel(const float* __restrict__ trans)
{
    __shared__ float aS[(SS + 1) * LL];
    __shared__ float tS[LL * LL];
    __shared__ unsigned char bpS[SS * LL];

    const int b = blockIdx.x / CC, c = blockIdx.x % CC;
    int nbp = stage_and_bp(b, c, aS, tS, bpS, trans);

    if (threadIdx.x < LL) {
        int cur = threadIdx.x;
        for (int i = nbp - 1; i >= 0; i--) cur = bpS[i * LL + cur];
        g_comp[(b * CC + c) * LL + threadIdx.x] = (unsigned char)cur;
    }
}

// ---------------------------------------------------------------------------
// Boundary walk: final argmax (score, last_tag) + 16-step composition chain.
// ---------------------------------------------------------------------------
__global__ void __launch_bounds__(32) boundary_kernel(float* __restrict__ out)
{
    __shared__ unsigned char compS[CC * LL];
    const int b = blockIdx.x;
    const int l = threadIdx.x;

    float al = (l < LL) ? g_alpha[((size_t)b * TT + TT - 1) * LL + l] : -3.0e38f;
    float fs[LL];
#pragma unroll
    for (int j = 0; j < LL; j++) fs[j] = __shfl_sync(0xFFFFFFFFu, al, j);
    float score; int last_tag;
    argmax17(fs, score, last_tag);

    for (int i = l; i < CC * LL; i += 32) compS[i] = g_comp[b * CC * LL + i];
    __syncthreads();

    if (l == 0) {
        out[BB * TT + b] = score;
        out[BB * TT + BB + b] = (float)TT;
        g_btag[b * 17 + 16] = (unsigned char)last_tag;
        int cur = last_tag;
        for (int c = CC - 1; c >= 0; c--) {
            cur = compS[c * LL + cur];
            g_btag[b * 17 + c] = (unsigned char)cur;
        }
    }
}

// ---------------------------------------------------------------------------
// Per-chunk backtrack + tag write (parallel over (b, chunk)).
// ---------------------------------------------------------------------------
__global__ void __launch_bounds__(128) tags_kernel(
    const float* __restrict__ trans, float* __restrict__ out)
{
    __shared__ float aS[(SS + 1) * LL];
    __shared__ float tS[LL * LL];
    __shared__ unsigned char bpS[SS * LL];
    __shared__ unsigned char tagS[SS];

    const int b = blockIdx.x / CC, c = blockIdx.x % CC;
    int nbp = stage_and_bp(b, c, aS, tS, bpS, trans);

    if (threadIdx.x == 0) {
        int cur = g_btag[b * 17 + c + 1];   // tag at t = 128*(c+1) (or last_tag for c=15)
        if (c == CC - 1) tagS[SS - 1] = (unsigned char)cur;
        for (int i = nbp - 1; i >= 0; i--) {
            cur = bpS[i * LL + cur];
            tagS[i] = (unsigned char)cur;
        }
    }
    __syncthreads();
    out[(size_t)b * TT + c * SS + threadIdx.x] = (float)tagS[threadIdx.x];
}

// ---------------------------------------------------------------------------
extern "C" void kernel_launch(void* const* d_in, const int* in_sizes, int n_in,
                              void* d_out, int out_size)
{
    (void)in_sizes; (void)n_in; (void)out_size;
    const void*  text  = d_in[0];
    const float* emb   = (const float*)d_in[1];
    const float* W5    = (const float*)d_in[2];
    const float* b5    = (const float*)d_in[3];
    const float* trans = (const float*)d_in[4];
    float* out = (float*)d_out;

    detect_kernel<<<1, 128>>>((const unsigned long long*)text);
    emis_kernel<<<(BB * TT) / 128, 128>>>(text, emb, W5, b5);
    forward_kernel<<<BB, 32>>>(trans);
    comp_kernel<<<BB * CC, 128>>>(trans);
    boundary_kernel<<<BB, 32>>>(out);
    tags_kernel<<<BB * CC, 128>>>(trans, out);
}

// round 4
// speedup vs baseline: 2.3843x; 1.0424x over previous
#include <cuda_runtime.h>
#include <cstdint>

#define BB 32
#define TT 2048
#define LL 17
#define EE 128
#define VV 100000
#define SS 128        // chunk length for backtracking
#define CC 16         // number of chunks (TT / SS)

// Scratch
__device__ float g_em[BB * TT * LL + 32];       // emissions [b][t][17] (+pad for prefetch overrun)
__device__ float g_alpha[BB * TT * LL];         // forward alphas [b][t][17]
__device__ unsigned char g_bp[BB * TT * LL];    // backpointers  [b][t-1][17]
__device__ unsigned char g_comp[BB * CC * LL];  // chunk survivor maps

// ---------------------------------------------------------------------------
// a + b via FFMA with imm multiplier 1.0 (rt_SMSP=1 vs FADD's 2).
// a*1.0 is exact, single rounding -> bitwise identical to FADD.
// ---------------------------------------------------------------------------
__device__ __forceinline__ float fadd1(float a, float b) {
    float r;
    asm("fma.rn.f32 %0, %1, 0f3F800000, %2;" : "=f"(r) : "f"(a), "f"(b));
    return r;
}

// ---------------------------------------------------------------------------
// Emissions: em[token][l] = dot(emb[text[token]], W5[:,l]) + b5[l]
// Per-block inline int64-vs-int32 detection of `text` (deterministic).
// ---------------------------------------------------------------------------
__device__ __forceinline__ void fma4(float4& a, float xe, const float4 w) {
    a.x += xe * w.x; a.y += xe * w.y; a.z += xe * w.z; a.w += xe * w.w;
}

__global__ void __launch_bounds__(128) emis_kernel(
    const void* __restrict__ textp,
    const float* __restrict__ emb,
    const float* __restrict__ W5,
    const float* __restrict__ b5)
{
    __shared__ float sW[EE * 20];
    __shared__ float sb[20];
    int tid = threadIdx.x;

    // dtype detection: all of the first 512 u64 words < V  <=>  int64 storage
    const unsigned long long* t64 = (const unsigned long long*)textp;
    int ok = 1;
    for (int i = tid; i < 512; i += 128)
        if (t64[i] >= (unsigned long long)VV) ok = 0;

    for (int i = tid; i < EE * 20; i += blockDim.x) sW[i] = 0.0f;
    if (tid < 20) sb[tid] = 0.0f;
    int is64 = __syncthreads_and(ok);
    for (int i = tid; i < EE * LL; i += blockDim.x) {
        int e = i / LL, l = i % LL;
        sW[e * 20 + l] = W5[i];
    }
    if (tid < LL) sb[tid] = b5[tid];
    __syncthreads();

    int token = blockIdx.x * blockDim.x + tid;
    int idx;
    if (is64) idx = (int)((const unsigned long long*)textp)[token];
    else      idx = ((const int*)textp)[token];
    idx = max(0, min(VV - 1, idx));

    const float4* row = (const float4*)(emb + (size_t)idx * EE);
    float4 a0 = *(const float4*)&sb[0];
    float4 a1 = *(const float4*)&sb[4];
    float4 a2 = *(const float4*)&sb[8];
    float4 a3 = *(const float4*)&sb[12];
    float4 a4 = *(const float4*)&sb[16];

#pragma unroll 4
    for (int e4 = 0; e4 < EE / 4; e4++) {
        float4 x = __ldg(&row[e4]);
        const float* wb = &sW[e4 * 4 * 20];
#pragma unroll
        for (int c = 0; c < 4; c++) {
            float xe = (c == 0) ? x.x : (c == 1) ? x.y : (c == 2) ? x.z : x.w;
            const float4* w4 = (const float4*)(wb + c * 20);
            fma4(a0, xe, w4[0]);
            fma4(a1, xe, w4[1]);
            fma4(a2, xe, w4[2]);
            fma4(a3, xe, w4[3]);
            fma4(a4, xe, w4[4]);
        }
    }

    float* o = g_em + (size_t)token * LL;
    o[0] = a0.x; o[1] = a0.y; o[2] = a0.z; o[3] = a0.w;
    o[4] = a1.x; o[5] = a1.y; o[6] = a1.z; o[7] = a1.w;
    o[8] = a2.x; o[9] = a2.y; o[10] = a2.z; o[11] = a2.w;
    o[12] = a3.x; o[13] = a3.y; o[14] = a3.z; o[15] = a3.w;
    o[16] = a4.x;
}

// ---------------------------------------------------------------------------
// argmax over 17 values, FIRST-index tie-break (matches jnp.argmax).
// ---------------------------------------------------------------------------
__device__ __forceinline__ void argmax17(const float* s, float& bv, int& bi) {
    float v[9]; int ix[9];
#pragma unroll
    for (int k = 0; k < 8; k++) {
        bool g = s[2 * k + 1] > s[2 * k];
        v[k]  = g ? s[2 * k + 1] : s[2 * k];
        ix[k] = g ? 2 * k + 1 : 2 * k;
    }
    v[8] = s[16]; ix[8] = 16;
#pragma unroll
    for (int k = 0; k < 4; k++) {
        bool g = v[2 * k + 1] > v[2 * k];
        v[k]  = g ? v[2 * k + 1] : v[2 * k];
        ix[k] = g ? ix[2 * k + 1] : ix[2 * k];
    }
    { bool g = v[1] > v[0]; v[0] = g ? v[1] : v[0]; ix[0] = g ? ix[1] : ix[0]; }
    { bool g = v[3] > v[2]; v[2] = g ? v[3] : v[2]; ix[2] = g ? ix[3] : ix[2]; }
    { bool g = v[2] > v[0]; v[0] = g ? v[2] : v[0]; ix[0] = g ? ix[2] : ix[0]; }
    { bool g = v[8] > v[0]; v[0] = g ? v[8] : v[0]; ix[0] = g ? ix[8] : ix[0]; }
    bv = v[0]; bi = ix[0];
}

// Max-only step (max is exactly associative -> bitwise reference value).
__device__ __forceinline__ float step_max(float alpha, const float* trc) {
    float s[LL];
#pragma unroll
    for (int j = 0; j < LL; j++)
        s[j] = fadd1(__shfl_sync(0xFFFFFFFFu, alpha, j), trc[j]);
    float v[9];
#pragma unroll
    for (int k = 0; k < 8; k++) v[k] = fmaxf(s[2 * k], s[2 * k + 1]);
    v[8] = s[16];
#pragma unroll
    for (int k = 0; k < 4; k++) v[k] = fmaxf(v[2 * k], v[2 * k + 1]);
    v[0] = fmaxf(v[0], v[1]); v[2] = fmaxf(v[2], v[3]);
    v[0] = fmaxf(v[0], v[2]);
    return fmaxf(v[0], v[8]);
}

// ---------------------------------------------------------------------------
// Forward chain: one warp per batch, lane = label. Max-only,
// depth-16 em prefetch ring, stores alpha vector per step.
// ---------------------------------------------------------------------------
__global__ void __launch_bounds__(32, 1) forward_kernel(
    const float* __restrict__ trans)
{
    const int b = blockIdx.x;
    const int l = threadIdx.x;
    const int le = (l < LL) ? l : 0;
    const bool act = (l < LL);

    float trc[LL];
#pragma unroll
    for (int j = 0; j < LL; j++) trc[j] = act ? trans[j * LL + le] : 0.0f;

    const float* em = g_em + (size_t)b * TT * LL;
    float alpha = act ? em[le] : -3.0e38f;
    float* pa = g_alpha + (size_t)b * TT * LL + l;
    if (act) pa[0] = alpha;

    float ring[16];
    const float* pe = em + LL + le;
#pragma unroll
    for (int i = 0; i < 16; i++) ring[i] = __ldg(pe + i * LL);
    const float* pf = pe + 16 * LL;
    float* ps = pa + LL;

    for (int blk = 0; blk < 127; blk++) {
#pragma unroll
        for (int u = 0; u < 16; u++) {
            float emc = ring[u];
            ring[u] = __ldg(pf + u * LL);           // t+16 (pad covers overrun)
            alpha = fadd1(step_max(alpha, trc), emc);
            if (act) ps[u * LL] = alpha;
        }
        pf += 16 * LL;
        ps += 16 * LL;
    }
#pragma unroll
    for (int u = 0; u < 15; u++) {
        alpha = fadd1(step_max(alpha, trc), ring[u]);
        if (act) ps[u * LL] = alpha;
    }
}

// ---------------------------------------------------------------------------
// bp_kernel: per (b, chunk) recompute backpointers from stored alphas
// (bitwise identical to reference scores), write to g_bp, and build the
// chunk survivor composition map -> g_comp.
// ---------------------------------------------------------------------------
__global__ void __launch_bounds__(128) bp_kernel(const float* __restrict__ trans)
{
    __shared__ float aS[(SS + 1) * LL];
    __shared__ float tS[LL * LL];
    __shared__ unsigned char bpS[SS * LL];

    const int tid = threadIdx.x;
    const int b = blockIdx.x / CC, c = blockIdx.x % CC;
    const int t0 = c * SS;
    const int nrows = (c == CC - 1) ? SS : (SS + 1);
    const int nbp   = (c == CC - 1) ? (SS - 1) : SS;

    const float* src = g_alpha + ((size_t)b * TT + t0) * LL;
    for (int i = tid; i < nrows * LL; i += 128) aS[i] = src[i];
    for (int i = tid; i < LL * LL; i += 128) tS[i] = trans[i];
    __syncthreads();

    if (tid < nbp) {
        float a[LL];
#pragma unroll
        for (int k = 0; k < LL; k++) a[k] = aS[tid * LL + k];
#pragma unroll 1
        for (int lcur = 0; lcur < LL; lcur++) {
            float s[LL];
#pragma unroll
            for (int k = 0; k < LL; k++) s[k] = a[k] + tS[k * LL + lcur];
            float bv; int bi;
            argmax17(s, bv, bi);
            bpS[tid * LL + lcur] = (unsigned char)bi;
        }
    }
    __syncthreads();

    unsigned char* bdst = g_bp + ((size_t)b * TT + t0) * LL;
    for (int i = tid; i < nbp * LL; i += 128) bdst[i] = bpS[i];

    if (tid < LL) {
        int cur = tid;
        for (int i = nbp - 1; i >= 0; i--) cur = bpS[i * LL + cur];
        g_comp[(b * CC + c) * LL + tid] = (unsigned char)cur;
    }
}

// ---------------------------------------------------------------------------
// tags_kernel: per (b, chunk). Redundantly derives the boundary tag via the
// comp-map chain, walks its 128-step chunk, writes tags; block c==0 also
// writes score and text_lens.
// ---------------------------------------------------------------------------
__global__ void __launch_bounds__(128) tags_kernel(float* __restrict__ out)
{
    __shared__ unsigned char bpS[SS * LL];
    __shared__ unsigned char compS[CC * LL];
    __shared__ float afin[LL];
    __shared__ unsigned char tagS[SS];

    const int tid = threadIdx.x;
    const int b = blockIdx.x / CC, c = blockIdx.x % CC;
    const int t0 = c * SS;
    const int nbp = (c == CC - 1) ? (SS - 1) : SS;

    const unsigned char* bsrc = g_bp + ((size_t)b * TT + t0) * LL;
    for (int i = tid; i < nbp * LL; i += 128) bpS[i] = bsrc[i];
    for (int i = tid; i < CC * LL; i += 128) compS[i] = g_comp[b * CC * LL + i];
    if (tid < LL) afin[tid] = g_alpha[((size_t)b * TT + TT - 1) * LL + tid];
    __syncthreads();

    if (tid == 0) {
        // last_tag / score: first-index tie-break via strict >
        float bv = afin[0]; int bi = 0;
        for (int j = 1; j < LL; j++) if (afin[j] > bv) { bv = afin[j]; bi = j; }
        if (c == 0) {
            out[BB * TT + b] = bv;
            out[BB * TT + BB + b] = (float)TT;
        }
        // seed = tag at t = 128*(c+1)  (for c == 15: tag at t = 2047)
        int cur = bi;
        for (int cc = CC - 1; cc >= c + 1; cc--) cur = compS[cc * LL + cur];
        if (c == CC - 1) tagS[SS - 1] = (unsigned char)cur;
        for (int i = nbp - 1; i >= 0; i--) {
            cur = bpS[i * LL + cur];
            tagS[i] = (unsigned char)cur;
        }
    }
    __syncthreads();
    out[(size_t)b * TT + t0 + tid] = (float)tagS[tid];
}

// ---------------------------------------------------------------------------
extern "C" void kernel_launch(void* const* d_in, const int* in_sizes, int n_in,
                              void* d_out, int out_size)
{
    (void)in_sizes; (void)n_in; (void)out_size;
    const void*  text  = d_in[0];
    const float* emb   = (const float*)d_in[1];
    const float* W5    = (const float*)d_in[2];
    const float* b5    = (const float*)d_in[3];
    const float* trans = (const float*)d_in[4];
    float* out = (float*)d_out;

    emis_kernel<<<(BB * TT) / 128, 128>>>(text, emb, W5, b5);
    forward_kernel<<<BB, 32>>>(trans);
    bp_kernel<<<BB * CC, 128>>>(trans);
    tags_kernel<<<BB * CC, 128>>>(out);
}